// round 13
// baseline (speedup 1.0000x reference)
#include <cuda_runtime.h>
#include <cstdint>

#define NC   21
#define NC2  (NC * NC)
#define NB   8
#define HW   (512 * 512)
#define Q    (HW / 4)            // float4 groups per channel plane (65536)
#define TPB  512
#define GPB  512                 // groups per block (one float4 per thread)
#define NBLOCKS ((NB * Q) / GPB) // 1024; 128 blocks per sample, no straddle
#define D    2                   // smem ring depth (stages)
#define STAGE_BYTES (GPB * 16)   // 8192 per tensor per channel

// Scratch: per-sample confusion matrices conf[b][true][pred].
__device__ int g_conf[NB * NC2];
__device__ unsigned int g_done;   // zero-init; reset by last block each run

__device__ __forceinline__ void mbar_init(uint32_t mbar, uint32_t count) {
    asm volatile("mbarrier.init.shared.b64 [%0], %1;" :: "r"(mbar), "r"(count) : "memory");
}
__device__ __forceinline__ void mbar_expect_tx(uint32_t mbar, uint32_t bytes) {
    asm volatile("mbarrier.arrive.expect_tx.shared.b64 _, [%0], %1;"
                 :: "r"(mbar), "r"(bytes) : "memory");
}
__device__ __forceinline__ void mbar_wait(uint32_t mbar, uint32_t parity) {
    asm volatile(
        "{\n\t.reg .pred P;\n\t"
        "WL_%=:\n\t"
        "mbarrier.try_wait.parity.acquire.cta.shared::cta.b64 P, [%0], %1, 0x989680;\n\t"
        "@P bra WD_%=;\n\t"
        "bra WL_%=;\n\t"
        "WD_%=:\n\t}"
        :: "r"(mbar), "r"(parity) : "memory");
}
__device__ __forceinline__ void bulk_g2s(uint32_t dst_smem, const void* src, uint32_t bytes,
                                         uint32_t mbar) {
    asm volatile(
        "cp.async.bulk.shared::cta.global.mbarrier::complete_tx::bytes [%0], [%1], %2, [%3];"
        :: "r"(dst_smem), "l"(src), "r"(bytes), "r"(mbar) : "memory");
}

__global__ void __launch_bounds__(TPB, 3)
conf_kernel(const float* __restrict__ pred,
            const float* __restrict__ tgt,
            float* __restrict__ out) {
    __shared__ alignas(16) float4 bufP[D][GPB];
    __shared__ alignas(16) float4 bufT[D][GPB];
    __shared__ alignas(8) unsigned long long mbar_full[D];
    __shared__ int sconf[NC2];

    const int tid = threadIdx.x;
    for (int i = tid; i < NC2; i += TPB) sconf[i] = 0;

    const int b = blockIdx.x >> 7;               // 128 blocks per sample
    const int tilebase = (blockIdx.x & 127) * GPB;
    const float4* pp = reinterpret_cast<const float4*>(pred) + (size_t)b * NC * Q + tilebase;
    const float4* tp = reinterpret_cast<const float4*>(tgt)  + (size_t)b * NC * Q + tilebase;

    uint32_t sP = (uint32_t)__cvta_generic_to_shared(&bufP[0][0]);
    uint32_t sT = (uint32_t)__cvta_generic_to_shared(&bufT[0][0]);
    uint32_t sM = (uint32_t)__cvta_generic_to_shared(&mbar_full[0]);

    if (tid == 0) {
        mbar_init(sM + 0, 1);
        mbar_init(sM + 8, 1);
        asm volatile("fence.proxy.async.shared::cta;" ::: "memory");
    }
    __syncthreads();

    // Prologue: stages for channels 0 and 1 in flight.
    if (tid == 0) {
        #pragma unroll
        for (int s = 0; s < D; s++) {
            mbar_expect_tx(sM + s * 8, 2 * STAGE_BYTES);
            bulk_g2s(sP + s * STAGE_BYTES, pp + (size_t)s * Q, STAGE_BYTES, sM + s * 8);
            bulk_g2s(sT + s * STAGE_BYTES, tp + (size_t)s * Q, STAGE_BYTES, sM + s * 8);
        }
    }

    float4 pm, tm;
    int pax = 0, pay = 0, paz = 0, paw = 0;
    int tax = 0, tay = 0, taz = 0, taw = 0;

    #pragma unroll
    for (int c = 0; c < NC; c++) {
        const int s = c & (D - 1);
        const uint32_t ph = (c / D) & 1;
        mbar_wait(sM + s * 8, ph);

        float4 v = bufP[s][tid];
        float4 w = bufT[s][tid];

        __syncthreads();           // everyone has read slot s
        if (tid == 0 && c + D < NC) {
            mbar_expect_tx(sM + s * 8, 2 * STAGE_BYTES);
            bulk_g2s(sP + s * STAGE_BYTES, pp + (size_t)(c + D) * Q, STAGE_BYTES, sM + s * 8);
            bulk_g2s(sT + s * STAGE_BYTES, tp + (size_t)(c + D) * Q, STAGE_BYTES, sM + s * 8);
        }

        if (c == 0) { pm = v; tm = w; }
        else {
            if (v.x > pm.x) { pm.x = v.x; pax = c; }
            if (v.y > pm.y) { pm.y = v.y; pay = c; }
            if (v.z > pm.z) { pm.z = v.z; paz = c; }
            if (v.w > pm.w) { pm.w = v.w; paw = c; }
            if (w.x > tm.x) { tm.x = w.x; tax = c; }
            if (w.y > tm.y) { tm.y = w.y; tay = c; }
            if (w.z > tm.z) { tm.z = w.z; taz = c; }
            if (w.w > tm.w) { tm.w = w.w; taw = c; }
        }
    }

    atomicAdd(&sconf[tax * NC + pax], 1);
    atomicAdd(&sconf[tay * NC + pay], 1);
    atomicAdd(&sconf[taz * NC + paz], 1);
    atomicAdd(&sconf[taw * NC + paw], 1);

    __syncthreads();
    for (int i = tid; i < NC2; i += TPB) {
        int v = sconf[i];
        if (v) atomicAdd(&g_conf[b * NC2 + i], v);
    }

    // ---- last-block finalize ----
    __threadfence();
    __shared__ unsigned int s_rank;
    if (tid == 0) s_rank = atomicAdd(&g_done, 1u);
    __syncthreads();
    if (s_rank != NBLOCKS - 1) return;

    __shared__ float iou_sum[NB];
    __shared__ int   valid_cnt[NB];
    if (tid < NB) { iou_sum[tid] = 0.0f; valid_cnt[tid] = 0; }
    if (tid == 0) g_done = 0;               // reset for next invocation
    __syncthreads();

    if (tid < NB * NC) {
        int bb = tid / NC;
        int c  = tid - bb * NC;
        const int* cb = &g_conf[bb * NC2];
        int tpv = __ldcg(&cb[c * NC + c]);
        int row = 0, col = 0;
        #pragma unroll
        for (int k = 0; k < NC; k++) {
            row += __ldcg(&cb[c * NC + k]);   // TP + FN
            col += __ldcg(&cb[k * NC + c]);   // TP + FP
        }
        if (tpv > 0) {
            float iou = (float)tpv / (float)(row + col - tpv);
            atomicAdd(&iou_sum[bb], iou);
            atomicAdd(&valid_cnt[bb], 1);
        }
    }
    __syncthreads();

    // Re-zero scratch for the next invocation (all reads done above).
    for (int i = tid; i < NB * NC2; i += TPB) g_conf[i] = 0;

    if (tid == 0) {
        float s = 0.0f;
        #pragma unroll
        for (int bb = 0; bb < NB; bb++)
            s += iou_sum[bb] / fmaxf((float)valid_cnt[bb], 1.0f);
        out[0] = s / (float)NB;
    }
}

extern "C" void kernel_launch(void* const* d_in, const int* in_sizes, int n_in,
                              void* d_out, int out_size) {
    const float* pred = (const float*)d_in[0];
    const float* tgt  = (const float*)d_in[1];
    float* out = (float*)d_out;

    conf_kernel<<<NBLOCKS, TPB>>>(pred, tgt, out);
}

// round 14
// speedup vs baseline: 1.6087x; 1.6087x over previous
#include <cuda_runtime.h>

#define NC   21
#define NC2  (NC * NC)
#define NB   8
#define HW   (512 * 512)
#define Q    (HW / 4)            // float4 groups per channel plane (65536)
#define TPB  1024
#define NBLOCKS 148              // 1 CTA per SM, all resident: zero tail
#define NWT  16384               // total warp-tiles (32 groups = 512 B each)
#define WT_BASE (NWT / NBLOCKS)  // 110
#define WT_REM  (NWT % NBLOCKS)  // 104 blocks get one extra warp-tile

// Scratch: per-sample confusion matrices conf[b][true][pred].
// Zero at module load; the last block of each invocation re-zeroes after use.
__device__ int g_conf[NB * NC2];
__device__ unsigned int g_done;   // zero-init; reset by last block each run

// Streaming load, evict-first, 256B L2 granule (neutral but harmless).
__device__ __forceinline__ float4 ldcs256(const float4* p) {
    float4 v;
    asm volatile("ld.global.cs.L2::256B.v4.f32 {%0,%1,%2,%3}, [%4];"
                 : "=f"(v.x), "=f"(v.y), "=f"(v.z), "=f"(v.w)
                 : "l"(p));
    return v;
}

__global__ void __launch_bounds__(TPB, 1)
conf_kernel(const float* __restrict__ pred,
            const float* __restrict__ tgt,
            float* __restrict__ out) {
    __shared__ int sconf[2][NC2];   // two banks: chunk may straddle 1 sample boundary
    for (int i = threadIdx.x; i < 2 * NC2; i += TPB) (&sconf[0][0])[i] = 0;
    __syncthreads();

    const int j = blockIdx.x;
    const int wt = WT_BASE + (j < WT_REM ? 1 : 0);
    const int start = 32 * (j * WT_BASE + (j < WT_REM ? j : WT_REM));
    const int end = start + wt * 32;    // contiguous group range [start, end)

    for (int base = start; base < end; base += TPB) {
        int g = base + threadIdx.x;
        if (g < end) {
            int b = g >> 16;            // Q = 65536
            int p = g & (Q - 1);

            const float4* pp = reinterpret_cast<const float4*>(pred) + (size_t)b * NC * Q + p;
            const float4* tp = reinterpret_cast<const float4*>(tgt)  + (size_t)b * NC * Q + p;

            float4 pm = ldcs256(pp);
            float4 tm = ldcs256(tp);
            int pax = 0, pay = 0, paz = 0, paw = 0;
            int tax = 0, tay = 0, taz = 0, taw = 0;

            #pragma unroll
            for (int c = 1; c < NC; c++) {
                float4 v = ldcs256(pp + (size_t)c * Q);
                float4 w = ldcs256(tp + (size_t)c * Q);
                if (v.x > pm.x) { pm.x = v.x; pax = c; }
                if (v.y > pm.y) { pm.y = v.y; pay = c; }
                if (v.z > pm.z) { pm.z = v.z; paz = c; }
                if (v.w > pm.w) { pm.w = v.w; paw = c; }
                if (w.x > tm.x) { tm.x = w.x; tax = c; }
                if (w.y > tm.y) { tm.y = w.y; tay = c; }
                if (w.z > tm.z) { tm.z = w.z; taz = c; }
                if (w.w > tm.w) { tm.w = w.w; taw = c; }
            }

            int* sc = sconf[b & 1];
            atomicAdd(&sc[tax * NC + pax], 1);
            atomicAdd(&sc[tay * NC + pay], 1);
            atomicAdd(&sc[taz * NC + paz], 1);
            atomicAdd(&sc[taw * NC + paw], 1);
        }
    }

    __syncthreads();

    // Flush: map banks back to the (at most two) samples this block touched.
    const int b_lo = start >> 16;
    const int b_hi = (end - 1) >> 16;
    for (int i = threadIdx.x; i < NC2; i += TPB) {
        int v = sconf[b_lo & 1][i];
        if (v) atomicAdd(&g_conf[b_lo * NC2 + i], v);
        if (b_hi != b_lo) {
            int v2 = sconf[b_hi & 1][i];
            if (v2) atomicAdd(&g_conf[b_hi * NC2 + i], v2);
        }
    }

    // ---- last-block finalize ----
    __threadfence();
    __shared__ unsigned int s_rank;
    if (threadIdx.x == 0) s_rank = atomicAdd(&g_done, 1u);
    __syncthreads();
    if (s_rank != NBLOCKS - 1) return;

    __shared__ float iou_sum[NB];
    __shared__ int   valid_cnt[NB];
    int t = threadIdx.x;
    if (t < NB) { iou_sum[t] = 0.0f; valid_cnt[t] = 0; }
    if (t == 0) g_done = 0;                 // reset for next invocation
    __syncthreads();

    if (t < NB * NC) {
        int bb = t / NC;
        int c  = t - bb * NC;
        const int* cb = &g_conf[bb * NC2];
        int tpv = __ldcg(&cb[c * NC + c]);
        int row = 0, col = 0;
        #pragma unroll
        for (int k = 0; k < NC; k++) {
            row += __ldcg(&cb[c * NC + k]);   // TP + FN
            col += __ldcg(&cb[k * NC + c]);   // TP + FP
        }
        if (tpv > 0) {
            float iou = (float)tpv / (float)(row + col - tpv);
            atomicAdd(&iou_sum[bb], iou);
            atomicAdd(&valid_cnt[bb], 1);
        }
    }
    __syncthreads();

    // Re-zero scratch for the next invocation (all reads done above).
    for (int i = t; i < NB * NC2; i += TPB) g_conf[i] = 0;

    if (t == 0) {
        float s = 0.0f;
        #pragma unroll
        for (int bb = 0; bb < NB; bb++)
            s += iou_sum[bb] / fmaxf((float)valid_cnt[bb], 1.0f);
        out[0] = s / (float)NB;
    }
}

extern "C" void kernel_launch(void* const* d_in, const int* in_sizes, int n_in,
                              void* d_out, int out_size) {
    const float* pred = (const float*)d_in[0];
    const float* tgt  = (const float*)d_in[1];
    float* out = (float*)d_out;

    conf_kernel<<<NBLOCKS, TPB>>>(pred, tgt, out);
}